// round 9
// baseline (speedup 1.0000x reference)
#include <cuda_runtime.h>
#include <cstdint>

// Problem constants
#define CB    128
#define HH    56
#define WW    56
#define NPIX  3136
#define BATCH 8
#define NTOT  25088        // BATCH * NPIX
#define KTOT  1152         // CB * 9
#define OUTC  128

// Scratch
__device__ float g_off2[2][BATCH * 18 * NPIX];  // offset conv partial sums
__device__ float g_wt32[(size_t)OUTC * KTOT];   // tf32 weights, k' = n*128 + c

__device__ __forceinline__ float to_tf32(float f) {
    uint32_t u;
    asm("cvt.rna.tf32.f32 %0, %1;" : "=r"(u) : "f"(f));
    return __uint_as_float(u);
}
__device__ __forceinline__ uint32_t smem_u32(const void* p) {
    uint32_t a;
    asm("{ .reg .u64 t; cvta.to.shared.u64 t, %1; cvt.u32.u64 %0, t; }" : "=r"(a) : "l"(p));
    return a;
}
#define CP_ASYNC_CA(dst, src) \
    asm volatile("cp.async.ca.shared.global [%0], [%1], 16;" :: "r"(dst), "l"(src))
#define CP_COMMIT() asm volatile("cp.async.commit_group;" ::: "memory")
#define CP_WAIT(n)  asm volatile("cp.async.wait_group %0;" :: "n"(n) : "memory")

// ---------------------------------------------------------------------------
// Kernel 0: round weights to tf32 AND permute k: c*9+n -> n*128+c
// ---------------------------------------------------------------------------
__global__ void round_w_kernel(const float* __restrict__ w) {
    int i = blockIdx.x * blockDim.x + threadIdx.x;   // i = o*KTOT + c*9 + n
    if (i >= OUTC * KTOT) return;
    int o = i / KTOT;
    int r = i % KTOT;
    int c = r / 9;
    int n = r % 9;
    g_wt32[(size_t)o * KTOT + n * 128 + c] = to_tf32(__ldg(w + i));
}

// ---------------------------------------------------------------------------
// Kernel 1: offset conv, channel-split. 896 blocks x 128 threads.
// ---------------------------------------------------------------------------
#define OC_CCH 16

__global__ __launch_bounds__(128) void offset_conv_kernel(
        const float* __restrict__ x,
        const float* __restrict__ w,
        const float* __restrict__ bias) {
    __shared__ float xs[OC_CCH][3][60];
    __shared__ float ws[OC_CCH][18][9];

    int blk  = blockIdx.x;
    int half = blk & 1;
    int by   = blk >> 1;
    int b    = by / HH;
    int y    = by % HH;
    int tid  = threadIdx.x;
    int j     = tid / 7;
    int strip = tid % 7;
    bool active = tid < 126;

    for (int e = tid; e < OC_CCH * 3; e += 128) {
        int cc = e / 3, r = e % 3;
        xs[cc][r][0] = 0.f; xs[cc][r][57] = 0.f;
        xs[cc][r][58] = 0.f; xs[cc][r][59] = 0.f;
    }

    float acc[8];
    #pragma unroll
    for (int i = 0; i < 8; ++i) acc[i] = 0.f;

    const float* xb = x + (size_t)b * CB * NPIX;
    int cbeg = half * 64;

    for (int c0 = cbeg; c0 < cbeg + 64; c0 += OC_CCH) {
        __syncthreads();
        for (int e = tid; e < OC_CCH * 3 * WW; e += 128) {
            int cc  = e / (3 * WW);
            int r2  = e % (3 * WW);
            int r   = r2 / WW;
            int col = r2 % WW;
            int yy  = y - 1 + r;
            float v = 0.f;
            if (yy >= 0 && yy < HH)
                v = __ldg(xb + (size_t)(c0 + cc) * NPIX + yy * WW + col);
            xs[cc][r][col + 1] = v;
        }
        for (int e = tid; e < OC_CCH * 162; e += 128) {
            int cc = e / 162;
            int r2 = e % 162;
            ws[cc][r2 / 9][r2 % 9] = __ldg(w + (r2 / 9) * KTOT + (c0 + cc) * 9 + (r2 % 9));
        }
        __syncthreads();

        if (active) {
            #pragma unroll 4
            for (int cc = 0; cc < OC_CCH; ++cc) {
                float wr[9];
                #pragma unroll
                for (int t = 0; t < 9; ++t) wr[t] = ws[cc][j][t];
                #pragma unroll
                for (int ky = 0; ky < 3; ++ky) {
                    float rv[10];
                    #pragma unroll
                    for (int i = 0; i < 10; ++i) rv[i] = xs[cc][ky][strip * 8 + i];
                    #pragma unroll
                    for (int kx = 0; kx < 3; ++kx) {
                        float wv = wr[ky * 3 + kx];
                        #pragma unroll
                        for (int i = 0; i < 8; ++i)
                            acc[i] = fmaf(wv, rv[i + kx], acc[i]);
                    }
                }
            }
        }
    }

    if (active) {
        float bj = half ? 0.f : __ldg(bias + j);
        float* op = g_off2[half] + (size_t)(b * 18 + j) * NPIX + y * WW + strip * 8;
        #pragma unroll
        for (int i = 0; i < 8; ++i) op[i] = acc[i] + bj;
    }
}

// ---------------------------------------------------------------------------
// Kernel 2: FUSED sample + tf32 mma GEMM.
// B-build remapped for coalescing: thread = (channel = tid>>4, lane-pixel =
// tid&15); per i, 16 lanes read 16 CONSECUTIVE pixels of one channel row.
// Pipeline: build B(t) -> CP_WAIT(0) -> sync -> issue A(t+1) -> mma(t).
// ---------------------------------------------------------------------------
#define ROWF_A 20
#define ROWF_B 20
#define NCHUNK 72

__global__ __launch_bounds__(256, 3) void fused_gemm_kernel(
        const float* __restrict__ x, float* __restrict__ out) {
    __shared__ float4 wsm[64][9];                  // 9216 B
    __shared__ int4   osm[64][9];                  // 9216 B
    __shared__ float  As[2][128][ROWF_A];          // 20480 B
    __shared__ float  Bs[2][64][ROWF_B];           // 10240 B   total 49152 B

    int tid  = threadIdx.x;
    int wid  = tid >> 5;
    int lid  = tid & 31;
    int gid  = lid >> 2;
    int tig  = lid & 3;
    int warp_m = wid & 3;
    int warp_n = wid >> 2;

    int b    = blockIdx.x / 49;
    int tile = blockIdx.x % 49;
    int px0  = tile * 64;

    const float* xb = x + (size_t)b * CB * NPIX;

    // ---------------- Phase A: bilinear weight/offset tables ----------------
    for (int e = tid; e < 576; e += 256) {
        int np_l = e / 9, n = e % 9;
        int pix = px0 + np_l;
        int y = pix / WW, xw = pix % WW;

        size_t iy = (size_t)(b * 18 + n) * NPIX + pix;
        size_t ix = (size_t)(b * 18 + n + 9) * NPIX + pix;
        float off_y = g_off2[0][iy] + g_off2[1][iy];
        float off_x = g_off2[0][ix] + g_off2[1][ix];

        float p_y = (float)(y + n / 3) + off_y;
        float p_x = (float)(xw + n % 3) + off_x;

        float qy = floorf(p_y), qx = floorf(p_x);
        float qlt_y = fminf(fmaxf(qy, 0.f), 57.f);
        float qlt_x = fminf(fmaxf(qx, 0.f), 57.f);
        float qrb_y = fminf(fmaxf(qy + 1.f, 0.f), 57.f);
        float qrb_x = fminf(fmaxf(qx + 1.f, 0.f), 57.f);
        float py = fminf(fmaxf(p_y, 0.f), 57.f);
        float px = fminf(fmaxf(p_x, 0.f), 57.f);

        float g_lt = (1.f - (py - qlt_y)) * truncf(1.f - (px - qlt_x));
        float g_rb = (1.f - (qrb_y - py)) * truncf(1.f - (qrb_x - px));
        float g_lb = (1.f - (py - qlt_y)) * (1.f - (qrb_x - px));
        float g_rt = (1.f - (qrb_y - py)) * (1.f - (px - qlt_x));

        int iy_lt = (int)qlt_y, ix_lt = (int)qlt_x;
        int iy_rb = (int)qrb_y, ix_rb = (int)qrb_x;

        int o0 = (iy_lt - 1) * WW + (ix_lt - 1);
        int o1 = (iy_rb - 1) * WW + (ix_rb - 1);
        int o2 = (iy_lt - 1) * WW + (ix_rb - 1);
        int o3 = (iy_rb - 1) * WW + (ix_lt - 1);

        bool vy_lt = (iy_lt >= 1) && (iy_lt <= 56);
        bool vx_lt = (ix_lt >= 1) && (ix_lt <= 56);
        bool vy_rb = (iy_rb >= 1) && (iy_rb <= 56);
        bool vx_rb = (ix_rb >= 1) && (ix_rb <= 56);

        float w0 = (vy_lt && vx_lt) ? g_lt : 0.f;
        float w1 = (vy_rb && vx_rb) ? g_rb : 0.f;
        float w2 = (vy_lt && vx_rb) ? g_lb : 0.f;
        float w3 = (vy_rb && vx_lt) ? g_rt : 0.f;

        wsm[np_l][n] = make_float4(w0, w1, w2, w3);
        osm[np_l][n] = make_int4(o0, o1, o2, o3);
    }

    // A copy addressing: 2 x cp.async(16B) per thread per chunk
    int ar0 = tid >> 2;
    int ac0 = (tid & 3) * 4;
    const float* asrc0 = g_wt32 + (size_t)ar0 * KTOT + ac0;
    const float* asrc1 = asrc0 + (size_t)64 * KTOT;
    uint32_t smb = smem_u32(&As[0][0][0]);
    uint32_t adst0 = smb + (uint32_t)(ar0 * ROWF_A + ac0) * 4u;
    uint32_t adst1 = smb + (uint32_t)((ar0 + 64) * ROWF_A + ac0) * 4u;
    const uint32_t ASTAGE = 128u * ROWF_A * 4u;

    // B build addressing (coalesced): channel = tid>>4, lane pixel = tid&15
    int bch = tid >> 4;       // 0..15: channel within chunk
    int bpl = tid & 15;       // pixel lane; pixels bpl, 16+bpl, 32+bpl, 48+bpl

    float acc[2][4][4];
    #pragma unroll
    for (int mt = 0; mt < 2; ++mt)
        #pragma unroll
        for (int nt = 0; nt < 4; ++nt)
            #pragma unroll
            for (int r = 0; r < 4; ++r) acc[mt][nt][r] = 0.f;

    // prologue: A chunk 0
    CP_ASYNC_CA(adst0, asrc0);
    CP_ASYNC_CA(adst1, asrc1);
    CP_COMMIT();
    __syncthreads();    // tables ready

    int rA = warp_m * 32 + gid;
    int rB = warp_n * 32 + gid;

    for (int t = 0; t < NCHUNK; ++t) {
        int buf = t & 1;

        // build B tile: n = t/8, channel c = (t%8)*16 + bch; 4 pixels/thread.
        // For each i, lanes 0..15 read 16 consecutive pixels of one channel.
        {
            int n = t >> 3;
            int c = (t & 7) * 16 + bch;
            const float* xc = xb + (size_t)c * NPIX;
            #pragma unroll
            for (int i = 0; i < 4; ++i) {
                int p = i * 16 + bpl;
                float4 w4 = wsm[p][n];
                int4   o4 = osm[p][n];
                float s = 0.f;
                if (w4.x != 0.f) s = fmaf(w4.x, __ldg(xc + o4.x), s);
                if (w4.y != 0.f) s = fmaf(w4.y, __ldg(xc + o4.y), s);
                if (w4.z != 0.f) s = fmaf(w4.z, __ldg(xc + o4.z), s);
                if (w4.w != 0.f) s = fmaf(w4.w, __ldg(xc + o4.w), s);
                Bs[buf][p][bch] = to_tf32(s);
            }
        }

        CP_WAIT(0);          // A chunk t landed (issued one iteration ago)
        __syncthreads();

        // A prefetch AFTER the barrier (WAR-safe vs iter t-1 readers)
        if (t + 1 < NCHUNK) {
            uint32_t so = (uint32_t)((t + 1) & 1) * ASTAGE;
            CP_ASYNC_CA(adst0 + so, asrc0 + (t + 1) * 16);
            CP_ASYNC_CA(adst1 + so, asrc1 + (t + 1) * 16);
            CP_COMMIT();
        }

        const uint32_t* Asu = (const uint32_t*)&As[buf][0][0];
        const uint32_t* Bsu = (const uint32_t*)&Bs[buf][0][0];

        #pragma unroll
        for (int ks = 0; ks < 2; ++ks) {
            int k = ks * 8;
            uint32_t a[2][4];
            #pragma unroll
            for (int mt = 0; mt < 2; ++mt) {
                int r0 = rA + mt * 16;
                a[mt][0] = Asu[r0 * ROWF_A + k + tig];
                a[mt][1] = Asu[(r0 + 8) * ROWF_A + k + tig];
                a[mt][2] = Asu[r0 * ROWF_A + k + tig + 4];
                a[mt][3] = Asu[(r0 + 8) * ROWF_A + k + tig + 4];
            }
            uint32_t bb[4][2];
            #pragma unroll
            for (int nt = 0; nt < 4; ++nt) {
                int rn = rB + nt * 8;
                bb[nt][0] = Bsu[rn * ROWF_B + k + tig];
                bb[nt][1] = Bsu[rn * ROWF_B + k + tig + 4];
            }
            #pragma unroll
            for (int mt = 0; mt < 2; ++mt)
                #pragma unroll
                for (int nt = 0; nt < 4; ++nt) {
                    asm volatile(
                        "mma.sync.aligned.m16n8k8.row.col.f32.tf32.tf32.f32 "
                        "{%0,%1,%2,%3}, {%4,%5,%6,%7}, {%8,%9}, {%0,%1,%2,%3};"
                        : "+f"(acc[mt][nt][0]), "+f"(acc[mt][nt][1]),
                          "+f"(acc[mt][nt][2]), "+f"(acc[mt][nt][3])
                        : "r"(a[mt][0]), "r"(a[mt][1]), "r"(a[mt][2]), "r"(a[mt][3]),
                          "r"(bb[nt][0]), "r"(bb[nt][1]));
                }
        }
    }

    // epilogue
    #pragma unroll
    for (int mt = 0; mt < 2; ++mt) {
        #pragma unroll
        for (int half = 0; half < 2; ++half) {
            int o = rA + mt * 16 + half * 8;
            float* po = out + ((size_t)b * OUTC + o) * NPIX + px0;
            #pragma unroll
            for (int nt = 0; nt < 4; ++nt) {
                int col = warp_n * 32 + nt * 8 + 2 * tig;
                float2 v = make_float2(acc[mt][nt][half * 2], acc[mt][nt][half * 2 + 1]);
                *(float2*)(po + col) = v;
            }
        }
    }
}

// ---------------------------------------------------------------------------
extern "C" void kernel_launch(void* const* d_in, const int* in_sizes, int n_in,
                              void* d_out, int out_size) {
    const float* x  = (const float*)d_in[0];
    const float* ow = (const float*)d_in[1];
    const float* ob = (const float*)d_in[2];
    const float* cw = (const float*)d_in[3];
    float* out = (float*)d_out;

    round_w_kernel<<<(OUTC * KTOT + 1023) / 1024, 1024>>>(cw);
    offset_conv_kernel<<<BATCH * HH * 2, 128>>>(x, ow, ob);
    fused_gemm_kernel<<<NTOT / 64, 256>>>(x, out);
}

// round 11
// speedup vs baseline: 1.2593x; 1.2593x over previous
#include <cuda_runtime.h>
#include <cstdint>

// Problem constants
#define CB    128
#define HH    56
#define WW    56
#define NPIX  3136
#define BATCH 8
#define NTOT  25088        // BATCH * NPIX
#define KTOT  1152         // CB * 9
#define OUTC  128

// Scratch
__device__ float g_off2[2][BATCH * 18 * NPIX];  // offset conv partial sums (fp32!)
__device__ float g_wt32[(size_t)OUTC * KTOT];   // tf32 weights, k' = n*128 + c

__device__ __forceinline__ float to_tf32(float f) {
    uint32_t u;
    asm("cvt.rna.tf32.f32 %0, %1;" : "=r"(u) : "f"(f));
    return __uint_as_float(u);
}
__device__ __forceinline__ uint32_t smem_u32(const void* p) {
    uint32_t a;
    asm("{ .reg .u64 t; cvta.to.shared.u64 t, %1; cvt.u32.u64 %0, t; }" : "=r"(a) : "l"(p));
    return a;
}
#define CP_ASYNC_CA(dst, src) \
    asm volatile("cp.async.ca.shared.global [%0], [%1], 16;" :: "r"(dst), "l"(src))
#define CP_COMMIT() asm volatile("cp.async.commit_group;" ::: "memory")
#define CP_WAIT(n)  asm volatile("cp.async.wait_group %0;" :: "n"(n) : "memory")

// ---------------------------------------------------------------------------
// Kernel 0: round main weights to tf32, permute k: c*9+n -> n*128+c
// ---------------------------------------------------------------------------
__global__ void round_w_kernel(const float* __restrict__ w) {
    int i = blockIdx.x * blockDim.x + threadIdx.x;
    if (i >= OUTC * KTOT) return;
    int o = i / KTOT;
    int r = i % KTOT;
    int c = r / 9;
    int n = r % 9;
    g_wt32[(size_t)o * KTOT + n * 128 + c] = to_tf32(__ldg(w + i));
}

// ---------------------------------------------------------------------------
// Kernel 1: offset conv in FP32 (floor() discontinuity demands full precision).
// Channel-split: 896 blocks x 128 threads (R8 form, measured-good).
// ---------------------------------------------------------------------------
#define OC_CCH 16

__global__ __launch_bounds__(128) void offset_conv_kernel(
        const float* __restrict__ x,
        const float* __restrict__ w,
        const float* __restrict__ bias) {
    __shared__ float xs[OC_CCH][3][60];
    __shared__ float ws[OC_CCH][18][9];

    int blk  = blockIdx.x;
    int half = blk & 1;
    int by   = blk >> 1;
    int b    = by / HH;
    int y    = by % HH;
    int tid  = threadIdx.x;
    int j     = tid / 7;
    int strip = tid % 7;
    bool active = tid < 126;

    for (int e = tid; e < OC_CCH * 3; e += 128) {
        int cc = e / 3, r = e % 3;
        xs[cc][r][0] = 0.f; xs[cc][r][57] = 0.f;
        xs[cc][r][58] = 0.f; xs[cc][r][59] = 0.f;
    }

    float acc[8];
    #pragma unroll
    for (int i = 0; i < 8; ++i) acc[i] = 0.f;

    const float* xb = x + (size_t)b * CB * NPIX;
    int cbeg = half * 64;

    for (int c0 = cbeg; c0 < cbeg + 64; c0 += OC_CCH) {
        __syncthreads();
        for (int e = tid; e < OC_CCH * 3 * WW; e += 128) {
            int cc  = e / (3 * WW);
            int r2  = e % (3 * WW);
            int r   = r2 / WW;
            int col = r2 % WW;
            int yy  = y - 1 + r;
            float v = 0.f;
            if (yy >= 0 && yy < HH)
                v = __ldg(xb + (size_t)(c0 + cc) * NPIX + yy * WW + col);
            xs[cc][r][col + 1] = v;
        }
        for (int e = tid; e < OC_CCH * 162; e += 128) {
            int cc = e / 162;
            int r2 = e % 162;
            ws[cc][r2 / 9][r2 % 9] = __ldg(w + (r2 / 9) * KTOT + (c0 + cc) * 9 + (r2 % 9));
        }
        __syncthreads();

        if (active) {
            #pragma unroll 4
            for (int cc = 0; cc < OC_CCH; ++cc) {
                float wr[9];
                #pragma unroll
                for (int t = 0; t < 9; ++t) wr[t] = ws[cc][j][t];
                #pragma unroll
                for (int ky = 0; ky < 3; ++ky) {
                    float rv[10];
                    #pragma unroll
                    for (int i = 0; i < 10; ++i) rv[i] = xs[cc][ky][strip * 8 + i];
                    #pragma unroll
                    for (int kx = 0; kx < 3; ++kx) {
                        float wv = wr[ky * 3 + kx];
                        #pragma unroll
                        for (int i = 0; i < 8; ++i)
                            acc[i] = fmaf(wv, rv[i + kx], acc[i]);
                    }
                }
            }
        }
    }

    if (active) {
        float bj = half ? 0.f : __ldg(bias + j);
        float* op = g_off2[half] + (size_t)(b * 18 + j) * NPIX + y * WW + strip * 8;
        #pragma unroll
        for (int i = 0; i < 8; ++i) op[i] = acc[i] + bj;
    }
}

// ---------------------------------------------------------------------------
// Kernel 2: FUSED sample + tf32 mma GEMM.
// B-gather mapping v3: thread = (pixel p = tid&63 FIXED, channel group =
// tid>>6). Tables hoisted (1 LDS pair per chunk, like R8) AND each gather LDG
// has 32 lanes on 32 consecutive pixels of one channel (coalesced, like R9).
// Pipeline: build B(t) -> CP_WAIT(0) -> sync -> issue A(t+1) -> mma(t).
// ---------------------------------------------------------------------------
#define ROWF_A 20
#define ROWF_B 20
#define NCHUNK 72

__global__ __launch_bounds__(256, 3) void fused_gemm_kernel(
        const float* __restrict__ x, float* __restrict__ out) {
    __shared__ float4 wsm[64][9];                  // 9216 B
    __shared__ int4   osm[64][9];                  // 9216 B
    __shared__ float  As[2][128][ROWF_A];          // 20480 B
    __shared__ float  Bs[2][64][ROWF_B];           // 10240 B   total 49152 B

    int tid  = threadIdx.x;
    int wid  = tid >> 5;
    int lid  = tid & 31;
    int gid  = lid >> 2;
    int tig  = lid & 3;
    int warp_m = wid & 3;
    int warp_n = wid >> 2;

    int b    = blockIdx.x / 49;
    int tile = blockIdx.x % 49;
    int px0  = tile * 64;

    const float* xb = x + (size_t)b * CB * NPIX;

    // ---------------- Phase A: bilinear weight/offset tables ----------------
    for (int e = tid; e < 576; e += 256) {
        int np_l = e / 9, n = e % 9;
        int pix = px0 + np_l;
        int y = pix / WW, xw = pix % WW;

        size_t iy = (size_t)(b * 18 + n) * NPIX + pix;
        size_t ix = (size_t)(b * 18 + n + 9) * NPIX + pix;
        float off_y = g_off2[0][iy] + g_off2[1][iy];
        float off_x = g_off2[0][ix] + g_off2[1][ix];

        float p_y = (float)(y + n / 3) + off_y;
        float p_x = (float)(xw + n % 3) + off_x;

        float qy = floorf(p_y), qx = floorf(p_x);
        float qlt_y = fminf(fmaxf(qy, 0.f), 57.f);
        float qlt_x = fminf(fmaxf(qx, 0.f), 57.f);
        float qrb_y = fminf(fmaxf(qy + 1.f, 0.f), 57.f);
        float qrb_x = fminf(fmaxf(qx + 1.f, 0.f), 57.f);
        float py = fminf(fmaxf(p_y, 0.f), 57.f);
        float px = fminf(fmaxf(p_x, 0.f), 57.f);

        float g_lt = (1.f - (py - qlt_y)) * truncf(1.f - (px - qlt_x));
        float g_rb = (1.f - (qrb_y - py)) * truncf(1.f - (qrb_x - px));
        float g_lb = (1.f - (py - qlt_y)) * (1.f - (qrb_x - px));
        float g_rt = (1.f - (qrb_y - py)) * (1.f - (px - qlt_x));

        int iy_lt = (int)qlt_y, ix_lt = (int)qlt_x;
        int iy_rb = (int)qrb_y, ix_rb = (int)qrb_x;

        int o0 = (iy_lt - 1) * WW + (ix_lt - 1);
        int o1 = (iy_rb - 1) * WW + (ix_rb - 1);
        int o2 = (iy_lt - 1) * WW + (ix_rb - 1);
        int o3 = (iy_rb - 1) * WW + (ix_lt - 1);

        bool vy_lt = (iy_lt >= 1) && (iy_lt <= 56);
        bool vx_lt = (ix_lt >= 1) && (ix_lt <= 56);
        bool vy_rb = (iy_rb >= 1) && (iy_rb <= 56);
        bool vx_rb = (ix_rb >= 1) && (ix_rb <= 56);

        float w0 = (vy_lt && vx_lt) ? g_lt : 0.f;
        float w1 = (vy_rb && vx_rb) ? g_rb : 0.f;
        float w2 = (vy_lt && vx_rb) ? g_lb : 0.f;
        float w3 = (vy_rb && vx_lt) ? g_rt : 0.f;

        wsm[np_l][n] = make_float4(w0, w1, w2, w3);
        osm[np_l][n] = make_int4(o0, o1, o2, o3);
    }

    // A copy addressing: 2 x cp.async(16B) per thread per chunk
    int ar0 = tid >> 2;
    int ac0 = (tid & 3) * 4;
    const float* asrc0 = g_wt32 + (size_t)ar0 * KTOT + ac0;
    const float* asrc1 = asrc0 + (size_t)64 * KTOT;
    uint32_t smb = smem_u32(&As[0][0][0]);
    uint32_t adst0 = smb + (uint32_t)(ar0 * ROWF_A + ac0) * 4u;
    uint32_t adst1 = smb + (uint32_t)((ar0 + 64) * ROWF_A + ac0) * 4u;
    const uint32_t ASTAGE = 128u * ROWF_A * 4u;

    // B build addressing v3: pixel fixed per thread, channel group = tid>>6
    int bpx  = tid & 63;      // my pixel (0..63)
    int bcg  = tid >> 6;      // 0..3: channel group of 4

    float acc[2][4][4];
    #pragma unroll
    for (int mt = 0; mt < 2; ++mt)
        #pragma unroll
        for (int nt = 0; nt < 4; ++nt)
            #pragma unroll
            for (int r = 0; r < 4; ++r) acc[mt][nt][r] = 0.f;

    // prologue: A chunk 0
    CP_ASYNC_CA(adst0, asrc0);
    CP_ASYNC_CA(adst1, asrc1);
    CP_COMMIT();
    __syncthreads();    // tables ready

    int rA = warp_m * 32 + gid;
    int rB = warp_n * 32 + gid;

    for (int t = 0; t < NCHUNK; ++t) {
        int buf = t & 1;

        // build B tile: n = t/8, channels (t%8)*16 + bcg*4 + i for my pixel.
        // For each (i, tap): 32 lanes read 32 consecutive pixels of 1 channel.
        {
            int n  = t >> 3;
            int c0 = (t & 7) * 16 + bcg * 4;
            float4 w4 = wsm[bpx][n];
            int4   o4 = osm[bpx][n];
            const float* xc = xb + (size_t)c0 * NPIX;
            float v[4];
            #pragma unroll
            for (int i = 0; i < 4; ++i) {
                const float* xi = xc + (size_t)i * NPIX;
                float s = 0.f;
                if (w4.x != 0.f) s = fmaf(w4.x, __ldg(xi + o4.x), s);
                if (w4.y != 0.f) s = fmaf(w4.y, __ldg(xi + o4.y), s);
                if (w4.z != 0.f) s = fmaf(w4.z, __ldg(xi + o4.z), s);
                if (w4.w != 0.f) s = fmaf(w4.w, __ldg(xi + o4.w), s);
                v[i] = to_tf32(s);
            }
            *(float4*)&Bs[buf][bpx][bcg * 4] = make_float4(v[0], v[1], v[2], v[3]);
        }

        CP_WAIT(0);          // A chunk t landed (issued one iteration ago)
        __syncthreads();

        // A prefetch AFTER the barrier (WAR-safe vs iter t-1 readers)
        if (t + 1 < NCHUNK) {
            uint32_t so = (uint32_t)((t + 1) & 1) * ASTAGE;
            CP_ASYNC_CA(adst0 + so, asrc0 + (t + 1) * 16);
            CP_ASYNC_CA(adst1 + so, asrc1 + (t + 1) * 16);
            CP_COMMIT();
        }

        const uint32_t* Asu = (const uint32_t*)&As[buf][0][0];
        const uint32_t* Bsu = (const uint32_t*)&Bs[buf][0][0];

        #pragma unroll
        for (int ks = 0; ks < 2; ++ks) {
            int k = ks * 8;
            uint32_t a[2][4];
            #pragma unroll
            for (int mt = 0; mt < 2; ++mt) {
                int r0 = rA + mt * 16;
                a[mt][0] = Asu[r0 * ROWF_A + k + tig];
                a[mt][1] = Asu[(r0 + 8) * ROWF_A + k + tig];
                a[mt][2] = Asu[r0 * ROWF_A + k + tig + 4];
                a[mt][3] = Asu[(r0 + 8) * ROWF_A + k + tig + 4];
            }
            uint32_t bb[4][2];
            #pragma unroll
            for (int nt = 0; nt < 4; ++nt) {
                int rn = rB + nt * 8;
                bb[nt][0] = Bsu[rn * ROWF_B + k + tig];
                bb[nt][1] = Bsu[rn * ROWF_B + k + tig + 4];
            }
            #pragma unroll
            for (int mt = 0; mt < 2; ++mt)
                #pragma unroll
                for (int nt = 0; nt < 4; ++nt) {
                    asm volatile(
                        "mma.sync.aligned.m16n8k8.row.col.f32.tf32.tf32.f32 "
                        "{%0,%1,%2,%3}, {%4,%5,%6,%7}, {%8,%9}, {%0,%1,%2,%3};"
                        : "+f"(acc[mt][nt][0]), "+f"(acc[mt][nt][1]),
                          "+f"(acc[mt][nt][2]), "+f"(acc[mt][nt][3])
                        : "r"(a[mt][0]), "r"(a[mt][1]), "r"(a[mt][2]), "r"(a[mt][3]),
                          "r"(bb[nt][0]), "r"(bb[nt][1]));
                }
        }
    }

    // epilogue
    #pragma unroll
    for (int mt = 0; mt < 2; ++mt) {
        #pragma unroll
        for (int half = 0; half < 2; ++half) {
            int o = rA + mt * 16 + half * 8;
            float* po = out + ((size_t)b * OUTC + o) * NPIX + px0;
            #pragma unroll
            for (int nt = 0; nt < 4; ++nt) {
                int col = warp_n * 32 + nt * 8 + 2 * tig;
                float2 v = make_float2(acc[mt][nt][half * 2], acc[mt][nt][half * 2 + 1]);
                *(float2*)(po + col) = v;
            }
        }
    }
}

// ---------------------------------------------------------------------------
extern "C" void kernel_launch(void* const* d_in, const int* in_sizes, int n_in,
                              void* d_out, int out_size) {
    const float* x  = (const float*)d_in[0];
    const float* ow = (const float*)d_in[1];
    const float* ob = (const float*)d_in[2];
    const float* cw = (const float*)d_in[3];
    float* out = (float*)d_out;

    round_w_kernel<<<(OUTC * KTOT + 1023) / 1024, 1024>>>(cw);
    offset_conv_kernel<<<BATCH * HH * 2, 128>>>(x, ow, ob);
    fused_gemm_kernel<<<NTOT / 64, 256>>>(x, out);
}

// round 12
// speedup vs baseline: 1.4512x; 1.1524x over previous
#include <cuda_runtime.h>
#include <cstdint>

// Problem constants
#define CB    128
#define HH    56
#define WW    56
#define NPIX  3136
#define BATCH 8
#define NTOT  25088        // BATCH * NPIX
#define KTOT  1152         // CB * 9
#define OUTC  128

// Scratch
__device__ float g_off2[2][BATCH * 18 * NPIX];  // offset conv partial sums (fp32)
__device__ float g_wt32[(size_t)OUTC * KTOT];   // tf32 weights, k' = n*128 + c

__device__ __forceinline__ float to_tf32(float f) {
    uint32_t u;
    asm("cvt.rna.tf32.f32 %0, %1;" : "=r"(u) : "f"(f));
    return __uint_as_float(u);
}
__device__ __forceinline__ uint32_t smem_u32(const void* p) {
    uint32_t a;
    asm("{ .reg .u64 t; cvta.to.shared.u64 t, %1; cvt.u32.u64 %0, t; }" : "=r"(a) : "l"(p));
    return a;
}
#define CP_ASYNC_CA(dst, src) \
    asm volatile("cp.async.ca.shared.global [%0], [%1], 16;" :: "r"(dst), "l"(src))
#define CP_COMMIT() asm volatile("cp.async.commit_group;" ::: "memory")
#define CP_WAIT(n)  asm volatile("cp.async.wait_group %0;" :: "n"(n) : "memory")
#define LDMATRIX_X4(r, addr) \
    asm volatile("ldmatrix.sync.aligned.m8n8.x4.shared.b16 {%0,%1,%2,%3}, [%4];" \
        : "=r"((r)[0]), "=r"((r)[1]), "=r"((r)[2]), "=r"((r)[3]) : "r"(addr))

// ---------------------------------------------------------------------------
// Kernel 0: round main weights to tf32, permute k: c*9+n -> n*128+c
// ---------------------------------------------------------------------------
__global__ void round_w_kernel(const float* __restrict__ w) {
    int i = blockIdx.x * blockDim.x + threadIdx.x;
    if (i >= OUTC * KTOT) return;
    int o = i / KTOT;
    int r = i % KTOT;
    int c = r / 9;
    int n = r % 9;
    g_wt32[(size_t)o * KTOT + n * 128 + c] = to_tf32(__ldg(w + i));
}

// ---------------------------------------------------------------------------
// Kernel 1: offset conv in FP32 (floor() discontinuity demands full precision).
// Channel-split: 896 blocks x 128 threads (measured-good R8 form).
// ---------------------------------------------------------------------------
#define OC_CCH 16

__global__ __launch_bounds__(128) void offset_conv_kernel(
        const float* __restrict__ x,
        const float* __restrict__ w,
        const float* __restrict__ bias) {
    __shared__ float xs[OC_CCH][3][60];
    __shared__ float ws[OC_CCH][18][9];

    int blk  = blockIdx.x;
    int half = blk & 1;
    int by   = blk >> 1;
    int b    = by / HH;
    int y    = by % HH;
    int tid  = threadIdx.x;
    int j     = tid / 7;
    int strip = tid % 7;
    bool active = tid < 126;

    for (int e = tid; e < OC_CCH * 3; e += 128) {
        int cc = e / 3, r = e % 3;
        xs[cc][r][0] = 0.f; xs[cc][r][57] = 0.f;
        xs[cc][r][58] = 0.f; xs[cc][r][59] = 0.f;
    }

    float acc[8];
    #pragma unroll
    for (int i = 0; i < 8; ++i) acc[i] = 0.f;

    const float* xb = x + (size_t)b * CB * NPIX;
    int cbeg = half * 64;

    for (int c0 = cbeg; c0 < cbeg + 64; c0 += OC_CCH) {
        __syncthreads();
        for (int e = tid; e < OC_CCH * 3 * WW; e += 128) {
            int cc  = e / (3 * WW);
            int r2  = e % (3 * WW);
            int r   = r2 / WW;
            int col = r2 % WW;
            int yy  = y - 1 + r;
            float v = 0.f;
            if (yy >= 0 && yy < HH)
                v = __ldg(xb + (size_t)(c0 + cc) * NPIX + yy * WW + col);
            xs[cc][r][col + 1] = v;
        }
        for (int e = tid; e < OC_CCH * 162; e += 128) {
            int cc = e / 162;
            int r2 = e % 162;
            ws[cc][r2 / 9][r2 % 9] = __ldg(w + (r2 / 9) * KTOT + (c0 + cc) * 9 + (r2 % 9));
        }
        __syncthreads();

        if (active) {
            #pragma unroll 4
            for (int cc = 0; cc < OC_CCH; ++cc) {
                float wr[9];
                #pragma unroll
                for (int t = 0; t < 9; ++t) wr[t] = ws[cc][j][t];
                #pragma unroll
                for (int ky = 0; ky < 3; ++ky) {
                    float rv[10];
                    #pragma unroll
                    for (int i = 0; i < 10; ++i) rv[i] = xs[cc][ky][strip * 8 + i];
                    #pragma unroll
                    for (int kx = 0; kx < 3; ++kx) {
                        float wv = wr[ky * 3 + kx];
                        #pragma unroll
                        for (int i = 0; i < 8; ++i)
                            acc[i] = fmaf(wv, rv[i + kx], acc[i]);
                    }
                }
            }
        }
    }

    if (active) {
        float bj = half ? 0.f : __ldg(bias + j);
        float* op = g_off2[half] + (size_t)(b * 18 + j) * NPIX + y * WW + strip * 8;
        #pragma unroll
        for (int i = 0; i < 8; ++i) op[i] = acc[i] + bj;
    }
}

// ---------------------------------------------------------------------------
// Kernel 2: FUSED sample + tf32 mma GEMM.
// Tap-merge: each (pixel, tap) reduces to exactly 2 (weight, offset) pairs
// (provable from the trunc-bilinear: taps in the same row can only coexist
// when clamp-collapsed to the same column). Gather = 2 unconditional LDG/ch.
// Fragment loads via ldmatrix.x4 (8x4-b32 view of m8n8.b16).
// Pipeline: build B(t) -> CP_WAIT(0) -> sync -> issue A(t+1) -> mma(t).
// ---------------------------------------------------------------------------
#define ROWF_A 20
#define ROWF_B 20
#define NCHUNK 72
#define ASTAGE_B (128u * ROWF_A * 4u)   // bytes per A stage
#define BSTAGE_B (64u * ROWF_B * 4u)    // bytes per B stage

__global__ __launch_bounds__(256, 3) void fused_gemm_kernel(
        const float* __restrict__ x, float* __restrict__ out) {
    __shared__ float2 wsm[64][9];                              // 4608 B
    __shared__ int2   osm[64][9];                              // 4608 B
    __shared__ __align__(16) float As[2][128][ROWF_A];         // 20480 B
    __shared__ __align__(16) float Bs[2][64][ROWF_B];          // 10240 B

    int tid  = threadIdx.x;
    int wid  = tid >> 5;
    int lid  = tid & 31;
    int gid  = lid >> 2;
    int tig  = lid & 3;
    int warp_m = wid & 3;
    int warp_n = wid >> 2;

    int b    = blockIdx.x / 49;
    int tile = blockIdx.x % 49;
    int px0  = tile * 64;

    const float* xb = x + (size_t)b * CB * NPIX;

    // ---------------- Phase A: merged bilinear tables ----------------
    for (int e = tid; e < 576; e += 256) {
        int np_l = e / 9, n = e % 9;
        int pix = px0 + np_l;
        int y = pix / WW, xw = pix % WW;

        size_t iy = (size_t)(b * 18 + n) * NPIX + pix;
        size_t ix = (size_t)(b * 18 + n + 9) * NPIX + pix;
        float off_y = g_off2[0][iy] + g_off2[1][iy];
        float off_x = g_off2[0][ix] + g_off2[1][ix];

        float p_y = (float)(y + n / 3) + off_y;
        float p_x = (float)(xw + n % 3) + off_x;

        float qy = floorf(p_y), qx = floorf(p_x);
        float qlt_y = fminf(fmaxf(qy, 0.f), 57.f);
        float qlt_x = fminf(fmaxf(qx, 0.f), 57.f);
        float qrb_y = fminf(fmaxf(qy + 1.f, 0.f), 57.f);
        float qrb_x = fminf(fmaxf(qx + 1.f, 0.f), 57.f);
        float py = fminf(fmaxf(p_y, 0.f), 57.f);
        float px = fminf(fmaxf(p_x, 0.f), 57.f);

        float g_lt = (1.f - (py - qlt_y)) * truncf(1.f - (px - qlt_x));
        float g_rb = (1.f - (qrb_y - py)) * truncf(1.f - (qrb_x - px));
        float g_lb = (1.f - (py - qlt_y)) * (1.f - (qrb_x - px));
        float g_rt = (1.f - (qrb_y - py)) * (1.f - (px - qlt_x));

        int iy_lt = (int)qlt_y, ix_lt = (int)qlt_x;
        int iy_rb = (int)qrb_y, ix_rb = (int)qrb_x;

        int o0 = (iy_lt - 1) * WW + (ix_lt - 1);
        int o1 = (iy_rb - 1) * WW + (ix_rb - 1);
        int o2 = (iy_lt - 1) * WW + (ix_rb - 1);
        int o3 = (iy_rb - 1) * WW + (ix_lt - 1);

        bool vy_lt = (iy_lt >= 1) && (iy_lt <= 56);
        bool vx_lt = (ix_lt >= 1) && (ix_lt <= 56);
        bool vy_rb = (iy_rb >= 1) && (iy_rb <= 56);
        bool vx_rb = (ix_rb >= 1) && (ix_rb <= 56);

        float w0 = (vy_lt && vx_lt) ? g_lt : 0.f;
        float w1 = (vy_rb && vx_rb) ? g_rb : 0.f;
        float w2 = (vy_lt && vx_rb) ? g_lb : 0.f;
        float w3 = (vy_rb && vx_lt) ? g_rt : 0.f;

        // merge: row lt_y taps {w0@o0, w2@o2} coexist only if o0==o2; same for rb_y
        float wA, wB; int oA, oB;
        if (o0 == o2)        { wA = w0 + w2; oA = o0; }
        else if (w0 != 0.f)  { wA = w0;      oA = o0; }
        else                 { wA = w2;      oA = o2; }
        if (wA == 0.f) oA = 0;
        if (o1 == o3)        { wB = w1 + w3; oB = o1; }
        else if (w1 != 0.f)  { wB = w1;      oB = o1; }
        else                 { wB = w3;      oB = o3; }
        if (wB == 0.f) oB = 0;

        wsm[np_l][n] = make_float2(wA, wB);
        osm[np_l][n] = make_int2(oA, oB);
    }

    // A copy addressing: 2 x cp.async(16B) per thread per chunk
    int ar0 = tid >> 2;
    int ac0 = (tid & 3) * 4;
    const float* asrc0 = g_wt32 + (size_t)ar0 * KTOT + ac0;
    const float* asrc1 = asrc0 + (size_t)64 * KTOT;
    uint32_t smbA = smem_u32(&As[0][0][0]);
    uint32_t smbB = smem_u32(&Bs[0][0][0]);
    uint32_t adst0 = smbA + (uint32_t)(ar0 * ROWF_A + ac0) * 4u;
    uint32_t adst1 = smbA + (uint32_t)((ar0 + 64) * ROWF_A + ac0) * 4u;

    // ldmatrix lane addresses (bytes)
    uint32_t aAddr = smbA + (uint32_t)((warp_m * 32 + (lid & 15)) * ROWF_A * 4)
                          + (uint32_t)((lid >> 4) << 4);
    uint32_t bAddr0 = smbB + (uint32_t)((warp_n * 32 + (lid & 7) + ((lid >> 4) << 3)) * ROWF_B * 4)
                           + (uint32_t)(((lid >> 3) & 1) << 4);
    uint32_t bAddr1 = bAddr0 + 16u * ROWF_B * 4u;

    // B build addressing: pixel fixed per thread, channel group = tid>>6
    int bpx  = tid & 63;
    int bcg  = tid >> 6;

    float acc[2][4][4];
    #pragma unroll
    for (int mt = 0; mt < 2; ++mt)
        #pragma unroll
        for (int nt = 0; nt < 4; ++nt)
            #pragma unroll
            for (int r = 0; r < 4; ++r) acc[mt][nt][r] = 0.f;

    // prologue: A chunk 0
    CP_ASYNC_CA(adst0, asrc0);
    CP_ASYNC_CA(adst1, asrc1);
    CP_COMMIT();
    __syncthreads();    // tables ready

    for (int t = 0; t < NCHUNK; ++t) {
        int buf = t & 1;

        // build B tile: n = t/8, channels (t%8)*16 + bcg*4 + i for my pixel.
        // 2 unconditional coalesced LDG per channel (merged taps).
        {
            int n  = t >> 3;
            int c0 = (t & 7) * 16 + bcg * 4;
            float2 wq = wsm[bpx][n];
            int2   oq = osm[bpx][n];
            const float* xc = xb + (size_t)c0 * NPIX;
            float v[4];
            #pragma unroll
            for (int i = 0; i < 4; ++i) {
                const float* xi = xc + (size_t)i * NPIX;
                v[i] = to_tf32(fmaf(wq.y, __ldg(xi + oq.y), wq.x * __ldg(xi + oq.x)));
            }
            *(float4*)&Bs[buf][bpx][bcg * 4] = make_float4(v[0], v[1], v[2], v[3]);
        }

        CP_WAIT(0);          // A chunk t landed (issued one iteration ago)
        __syncthreads();

        // A prefetch AFTER the barrier (WAR-safe vs iter t-1 readers)
        if (t + 1 < NCHUNK) {
            uint32_t so = (uint32_t)((t + 1) & 1) * ASTAGE_B;
            CP_ASYNC_CA(adst0 + so, asrc0 + (t + 1) * 16);
            CP_ASYNC_CA(adst1 + so, asrc1 + (t + 1) * 16);
            CP_COMMIT();
        }

        uint32_t aoff = (uint32_t)buf * ASTAGE_B;
        uint32_t boff = (uint32_t)buf * BSTAGE_B;

        #pragma unroll
        for (int ks = 0; ks < 2; ++ks) {
            uint32_t koff = (uint32_t)ks * 32u;   // k step = 8 floats
            uint32_t a0r[4], a1r[4], b0r[4], b1r[4];
            LDMATRIX_X4(a0r, aAddr + aoff + koff);                       // mt=0
            LDMATRIX_X4(a1r, aAddr + aoff + koff + 16u * ROWF_A * 4u);   // mt=1
            LDMATRIX_X4(b0r, bAddr0 + boff + koff);                      // nt=0,1
            LDMATRIX_X4(b1r, bAddr1 + boff + koff);                      // nt=2,3

            const uint32_t* afr[2] = {a0r, a1r};
            uint32_t bfr[4][2] = {{b0r[0], b0r[1]}, {b0r[2], b0r[3]},
                                  {b1r[0], b1r[1]}, {b1r[2], b1r[3]}};
            #pragma unroll
            for (int mt = 0; mt < 2; ++mt)
                #pragma unroll
                for (int nt = 0; nt < 4; ++nt) {
                    asm volatile(
                        "mma.sync.aligned.m16n8k8.row.col.f32.tf32.tf32.f32 "
                        "{%0,%1,%2,%3}, {%4,%5,%6,%7}, {%8,%9}, {%0,%1,%2,%3};"
                        : "+f"(acc[mt][nt][0]), "+f"(acc[mt][nt][1]),
                          "+f"(acc[mt][nt][2]), "+f"(acc[mt][nt][3])
                        : "r"(afr[mt][0]), "r"(afr[mt][1]), "r"(afr[mt][2]), "r"(afr[mt][3]),
                          "r"(bfr[nt][0]), "r"(bfr[nt][1]));
                }
        }
    }

    // epilogue
    int rA = warp_m * 32 + gid;
    #pragma unroll
    for (int mt = 0; mt < 2; ++mt) {
        #pragma unroll
        for (int half = 0; half < 2; ++half) {
            int o = rA + mt * 16 + half * 8;
            float* po = out + ((size_t)b * OUTC + o) * NPIX + px0;
            #pragma unroll
            for (int nt = 0; nt < 4; ++nt) {
                int col = warp_n * 32 + nt * 8 + 2 * tig;
                float2 v = make_float2(acc[mt][nt][half * 2], acc[mt][nt][half * 2 + 1]);
                *(float2*)(po + col) = v;
            }
        }
    }
}

// ---------------------------------------------------------------------------
extern "C" void kernel_launch(void* const* d_in, const int* in_sizes, int n_in,
                              void* d_out, int out_size) {
    const float* x  = (const float*)d_in[0];
    const float* ow = (const float*)d_in[1];
    const float* ob = (const float*)d_in[2];
    const float* cw = (const float*)d_in[3];
    float* out = (float*)d_out;

    round_w_kernel<<<(OUTC * KTOT + 1023) / 1024, 1024>>>(cw);
    offset_conv_kernel<<<BATCH * HH * 2, 128>>>(x, ow, ob);
    fused_gemm_kernel<<<NTOT / 64, 256>>>(x, out);
}

// round 13
// speedup vs baseline: 1.5499x; 1.0680x over previous
#include <cuda_runtime.h>
#include <cstdint>

// Problem constants
#define CB    128
#define HH    56
#define WW    56
#define NPIX  3136
#define BATCH 8
#define NTOT  25088        // BATCH * NPIX
#define KTOT  1152         // CB * 9
#define OUTC  128

// Scratch
__device__ float g_off4[4][BATCH * 18 * NPIX];  // offset conv partial sums (fp32)
__device__ float g_wt32[(size_t)OUTC * KTOT];   // tf32 weights, k' = n*128 + c

__device__ __forceinline__ float to_tf32(float f) {
    uint32_t u;
    asm("cvt.rna.tf32.f32 %0, %1;" : "=r"(u) : "f"(f));
    return __uint_as_float(u);
}
__device__ __forceinline__ uint32_t smem_u32(const void* p) {
    uint32_t a;
    asm("{ .reg .u64 t; cvta.to.shared.u64 t, %1; cvt.u32.u64 %0, t; }" : "=r"(a) : "l"(p));
    return a;
}
#define CP_ASYNC_CA(dst, src) \
    asm volatile("cp.async.ca.shared.global [%0], [%1], 16;" :: "r"(dst), "l"(src))
#define CP_COMMIT() asm volatile("cp.async.commit_group;" ::: "memory")
#define CP_WAIT(n)  asm volatile("cp.async.wait_group %0;" :: "n"(n) : "memory")
#define LDMATRIX_X4(r, addr) \
    asm volatile("ldmatrix.sync.aligned.m8n8.x4.shared.b16 {%0,%1,%2,%3}, [%4];" \
        : "=r"((r)[0]), "=r"((r)[1]), "=r"((r)[2]), "=r"((r)[3]) : "r"(addr))

// ---------------------------------------------------------------------------
// Kernel 0: round main weights to tf32, permute k: c*9+n -> n*128+c
// ---------------------------------------------------------------------------
__global__ void round_w_kernel(const float* __restrict__ w) {
    int i = blockIdx.x * blockDim.x + threadIdx.x;
    if (i >= OUTC * KTOT) return;
    int o = i / KTOT;
    int r = i % KTOT;
    int c = r / 9;
    int n = r % 9;
    g_wt32[(size_t)o * KTOT + n * 128 + c] = to_tf32(__ldg(w + i));
}

// ---------------------------------------------------------------------------
// Kernel 1: offset conv FP32, quarter-split. 1792 blocks x 128 threads.
// Block = (b, y, quarter): partial sum over 32 channels -> g_off4[quarter].
// ---------------------------------------------------------------------------
#define OC_CCH 16

__global__ __launch_bounds__(128) void offset_conv_kernel(
        const float* __restrict__ x,
        const float* __restrict__ w,
        const float* __restrict__ bias) {
    __shared__ float xs[OC_CCH][3][60];
    __shared__ float ws[OC_CCH][18][9];

    int blk  = blockIdx.x;
    int q    = blk & 3;
    int by   = blk >> 2;
    int b    = by / HH;
    int y    = by % HH;
    int tid  = threadIdx.x;
    int j     = tid / 7;
    int strip = tid % 7;
    bool active = tid < 126;

    for (int e = tid; e < OC_CCH * 3; e += 128) {
        int cc = e / 3, r = e % 3;
        xs[cc][r][0] = 0.f; xs[cc][r][57] = 0.f;
        xs[cc][r][58] = 0.f; xs[cc][r][59] = 0.f;
    }

    float acc[8];
    #pragma unroll
    for (int i = 0; i < 8; ++i) acc[i] = 0.f;

    const float* xb = x + (size_t)b * CB * NPIX;
    int cbeg = q * 32;

    for (int c0 = cbeg; c0 < cbeg + 32; c0 += OC_CCH) {
        __syncthreads();
        for (int e = tid; e < OC_CCH * 3 * WW; e += 128) {
            int cc  = e / (3 * WW);
            int r2  = e % (3 * WW);
            int r   = r2 / WW;
            int col = r2 % WW;
            int yy  = y - 1 + r;
            float v = 0.f;
            if (yy >= 0 && yy < HH)
                v = __ldg(xb + (size_t)(c0 + cc) * NPIX + yy * WW + col);
            xs[cc][r][col + 1] = v;
        }
        for (int e = tid; e < OC_CCH * 162; e += 128) {
            int cc = e / 162;
            int r2 = e % 162;
            ws[cc][r2 / 9][r2 % 9] = __ldg(w + (r2 / 9) * KTOT + (c0 + cc) * 9 + (r2 % 9));
        }
        __syncthreads();

        if (active) {
            #pragma unroll 4
            for (int cc = 0; cc < OC_CCH; ++cc) {
                float wr[9];
                #pragma unroll
                for (int t = 0; t < 9; ++t) wr[t] = ws[cc][j][t];
                #pragma unroll
                for (int ky = 0; ky < 3; ++ky) {
                    float rv[10];
                    #pragma unroll
                    for (int i = 0; i < 10; ++i) rv[i] = xs[cc][ky][strip * 8 + i];
                    #pragma unroll
                    for (int kx = 0; kx < 3; ++kx) {
                        float wv = wr[ky * 3 + kx];
                        #pragma unroll
                        for (int i = 0; i < 8; ++i)
                            acc[i] = fmaf(wv, rv[i + kx], acc[i]);
                    }
                }
            }
        }
    }

    if (active) {
        float bj = (q == 0) ? __ldg(bias + j) : 0.f;
        float* op = g_off4[q] + (size_t)(b * 18 + j) * NPIX + y * WW + strip * 8;
        #pragma unroll
        for (int i = 0; i < 8; ++i) op[i] = acc[i] + bj;
    }
}

// ---------------------------------------------------------------------------
// Kernel 2: FUSED sample + tf32 mma GEMM, BK=32 per iteration (36 iters).
// Dynamic smem layout (64512 B):
//   [0, 4608)        wsm  float2[64][9]   merged tap weights
//   [4608, 9216)     osm  int2[64][9]     merged tap offsets
//   [9216, 46080)    As   float[2][128][36]
//   [46080, 64512)   Bs   float[2][64][36]
// Pipeline per iter: build B(t) -> CP_WAIT(0) -> sync -> issue A(t+1) -> 4x mma.
// ---------------------------------------------------------------------------
#define ROWF 36
#define NCHUNK2 36
#define OFF_WSM 0u
#define OFF_OSM 4608u
#define OFF_AS  9216u
#define OFF_BS  46080u
#define ASTG (128u * ROWF * 4u)    // 18432 B per A stage
#define BSTG (64u * ROWF * 4u)     // 9216 B per B stage
#define SMEM_DYN (OFF_BS + 2u * BSTG)   // 64512

__global__ __launch_bounds__(256, 3) void fused_gemm_kernel(
        const float* __restrict__ x, float* __restrict__ out) {
    extern __shared__ __align__(16) unsigned char dyn[];
    float2* wsm = (float2*)(dyn + OFF_WSM);   // [64][9]
    int2*   osm = (int2*)(dyn + OFF_OSM);     // [64][9]

    int tid  = threadIdx.x;
    int wid  = tid >> 5;
    int lid  = tid & 31;
    int gid  = lid >> 2;
    int tig  = lid & 3;
    int warp_m = wid & 3;
    int warp_n = wid >> 2;

    int b    = blockIdx.x / 49;
    int tile = blockIdx.x % 49;
    int px0  = tile * 64;

    const float* xb = x + (size_t)b * CB * NPIX;

    // ---------------- Phase A: merged bilinear tables ----------------
    for (int e = tid; e < 576; e += 256) {
        int np_l = e / 9, n = e % 9;
        int pix = px0 + np_l;
        int y = pix / WW, xw = pix % WW;

        size_t iy = (size_t)(b * 18 + n) * NPIX + pix;
        size_t ix = (size_t)(b * 18 + n + 9) * NPIX + pix;
        float off_y = g_off4[0][iy] + g_off4[1][iy] + g_off4[2][iy] + g_off4[3][iy];
        float off_x = g_off4[0][ix] + g_off4[1][ix] + g_off4[2][ix] + g_off4[3][ix];

        float p_y = (float)(y + n / 3) + off_y;
        float p_x = (float)(xw + n % 3) + off_x;

        float qy = floorf(p_y), qx = floorf(p_x);
        float qlt_y = fminf(fmaxf(qy, 0.f), 57.f);
        float qlt_x = fminf(fmaxf(qx, 0.f), 57.f);
        float qrb_y = fminf(fmaxf(qy + 1.f, 0.f), 57.f);
        float qrb_x = fminf(fmaxf(qx + 1.f, 0.f), 57.f);
        float py = fminf(fmaxf(p_y, 0.f), 57.f);
        float px = fminf(fmaxf(p_x, 0.f), 57.f);

        float g_lt = (1.f - (py - qlt_y)) * truncf(1.f - (px - qlt_x));
        float g_rb = (1.f - (qrb_y - py)) * truncf(1.f - (qrb_x - px));
        float g_lb = (1.f - (py - qlt_y)) * (1.f - (qrb_x - px));
        float g_rt = (1.f - (qrb_y - py)) * (1.f - (px - qlt_x));

        int iy_lt = (int)qlt_y, ix_lt = (int)qlt_x;
        int iy_rb = (int)qrb_y, ix_rb = (int)qrb_x;

        int o0 = (iy_lt - 1) * WW + (ix_lt - 1);
        int o1 = (iy_rb - 1) * WW + (ix_rb - 1);
        int o2 = (iy_lt - 1) * WW + (ix_rb - 1);
        int o3 = (iy_rb - 1) * WW + (ix_lt - 1);

        bool vy_lt = (iy_lt >= 1) && (iy_lt <= 56);
        bool vx_lt = (ix_lt >= 1) && (ix_lt <= 56);
        bool vy_rb = (iy_rb >= 1) && (iy_rb <= 56);
        bool vx_rb = (ix_rb >= 1) && (ix_rb <= 56);

        float w0 = (vy_lt && vx_lt) ? g_lt : 0.f;
        float w1 = (vy_rb && vx_rb) ? g_rb : 0.f;
        float w2 = (vy_lt && vx_rb) ? g_lb : 0.f;
        float w3 = (vy_rb && vx_lt) ? g_rt : 0.f;

        float wA, wB; int oA, oB;
        if (o0 == o2)        { wA = w0 + w2; oA = o0; }
        else if (w0 != 0.f)  { wA = w0;      oA = o0; }
        else                 { wA = w2;      oA = o2; }
        if (wA == 0.f) oA = 0;
        if (o1 == o3)        { wB = w1 + w3; oB = o1; }
        else if (w1 != 0.f)  { wB = w1;      oB = o1; }
        else                 { wB = w3;      oB = o3; }
        if (wB == 0.f) oB = 0;

        wsm[np_l * 9 + n] = make_float2(wA, wB);
        osm[np_l * 9 + n] = make_int2(oA, oB);
    }

    // A copy addressing: 4 x cp.async(16B) per thread per chunk (128x32 floats)
    int arow = tid >> 3;            // 0..31 (+32*i)
    int acol = (tid & 7) * 4;       // 0..28
    const float* asrcT = g_wt32 + (size_t)arow * KTOT + acol;
    uint32_t smb  = smem_u32(dyn);
    uint32_t adstT = smb + OFF_AS + (uint32_t)(arow * ROWF + acol) * 4u;

    // ldmatrix lane addresses (bytes), row stride = ROWF*4 = 144
    uint32_t aAddr = smb + OFF_AS
                   + (uint32_t)((warp_m * 32 + (lid & 15)) * ROWF * 4)
                   + (uint32_t)((lid >> 4) << 4);
    uint32_t bAddr0 = smb + OFF_BS
                    + (uint32_t)((warp_n * 32 + (lid & 7) + ((lid >> 4) << 3)) * ROWF * 4)
                    + (uint32_t)(((lid >> 3) & 1) << 4);
    uint32_t bAddr1 = bAddr0 + 16u * ROWF * 4u;

    // B build addressing: pixel fixed per thread, channel group = tid>>6 (8 ch)
    int bpx  = tid & 63;
    int bcg  = tid >> 6;

    float acc[2][4][4];
    #pragma unroll
    for (int mt = 0; mt < 2; ++mt)
        #pragma unroll
        for (int nt = 0; nt < 4; ++nt)
            #pragma unroll
            for (int r = 0; r < 4; ++r) acc[mt][nt][r] = 0.f;

    // prologue: A chunk 0 into stage 0
    #pragma unroll
    for (int i = 0; i < 4; ++i)
        CP_ASYNC_CA(adstT + (uint32_t)(i * 32 * ROWF) * 4u, asrcT + (size_t)i * 32 * KTOT);
    CP_COMMIT();
    __syncthreads();    // tables ready

    for (int t = 0; t < NCHUNK2; ++t) {
        int buf = t & 1;

        // build B tile: n = t/4, channels (t%4)*32 + bcg*8 .. +7 for my pixel.
        {
            int n  = t >> 2;
            int c0 = (t & 3) * 32 + bcg * 8;
            float2 wq = wsm[bpx * 9 + n];
            int2   oq = osm[bpx * 9 + n];
            const float* xc = xb + (size_t)c0 * NPIX;
            float v[8];
            #pragma unroll
            for (int i = 0; i < 8; ++i) {
                const float* xi = xc + (size_t)i * NPIX;
                v[i] = to_tf32(fmaf(wq.y, __ldg(xi + oq.y), wq.x * __ldg(xi + oq.x)));
            }
            float* brow = (float*)(dyn + OFF_BS + (uint32_t)buf * BSTG) + bpx * ROWF + bcg * 8;
            *(float4*)(brow)     = make_float4(v[0], v[1], v[2], v[3]);
            *(float4*)(brow + 4) = make_float4(v[4], v[5], v[6], v[7]);
        }

        CP_WAIT(0);          // A chunk t landed (issued one iteration ago)
        __syncthreads();

        // A prefetch AFTER the barrier (WAR-safe vs iter t-1 readers)
        if (t + 1 < NCHUNK2) {
            uint32_t so = (uint32_t)((t + 1) & 1) * ASTG;
            const float* src = asrcT + (size_t)(t + 1) * 32;
            #pragma unroll
            for (int i = 0; i < 4; ++i)
                CP_ASYNC_CA(adstT + so + (uint32_t)(i * 32 * ROWF) * 4u,
                            src + (size_t)i * 32 * KTOT);
            CP_COMMIT();
        }

        uint32_t aoff = (uint32_t)buf * ASTG;
        uint32_t boff = (uint32_t)buf * BSTG;

        #pragma unroll
        for (int ks = 0; ks < 4; ++ks) {
            uint32_t koff = (uint32_t)ks * 32u;   // 8 floats per k-step
            uint32_t a0r[4], a1r[4], b0r[4], b1r[4];
            LDMATRIX_X4(a0r, aAddr + aoff + koff);
            LDMATRIX_X4(a1r, aAddr + aoff + koff + 16u * ROWF * 4u);
            LDMATRIX_X4(b0r, bAddr0 + boff + koff);
            LDMATRIX_X4(b1r, bAddr1 + boff + koff);

            const uint32_t* afr[2] = {a0r, a1r};
            uint32_t bfr[4][2] = {{b0r[0], b0r[1]}, {b0r[2], b0r[3]},
                                  {b1r[0], b1r[1]}, {b1r[2], b1r[3]}};
            #pragma unroll
            for (int mt = 0; mt < 2; ++mt)
                #pragma unroll
                for (int nt = 0; nt < 4; ++nt) {
                    asm volatile(
                        "mma.sync.aligned.m16n8k8.row.col.f32.tf32.tf32.f32 "
                        "{%0,%1,%2,%3}, {%4,%5,%6,%7}, {%8,%9}, {%0,%1,%2,%3};"
                        : "+f"(acc[mt][nt][0]), "+f"(acc[mt][nt][1]),
                          "+f"(acc[mt][nt][2]), "+f"(acc[mt][nt][3])
                        : "r"(afr[mt][0]), "r"(afr[mt][1]), "r"(afr[mt][2]), "r"(afr[mt][3]),
                          "r"(bfr[nt][0]), "r"(bfr[nt][1]));
                }
        }
    }

    // epilogue
    int rA = warp_m * 32 + gid;
    #pragma unroll
    for (int mt = 0; mt < 2; ++mt) {
        #pragma unroll
        for (int half = 0; half < 2; ++half) {
            int o = rA + mt * 16 + half * 8;
            float* po = out + ((size_t)b * OUTC + o) * NPIX + px0;
            #pragma unroll
            for (int nt = 0; nt < 4; ++nt) {
                int col = warp_n * 32 + nt * 8 + 2 * tig;
                float2 v = make_float2(acc[mt][nt][half * 2], acc[mt][nt][half * 2 + 1]);
                *(float2*)(po + col) = v;
            }
        }
    }
}

// ---------------------------------------------------------------------------
extern "C" void kernel_launch(void* const* d_in, const int* in_sizes, int n_in,
                              void* d_out, int out_size) {
    const float* x  = (const float*)d_in[0];
    const float* ow = (const float*)d_in[1];
    const float* ob = (const float*)d_in[2];
    const float* cw = (const float*)d_in[3];
    float* out = (float*)d_out;

    static bool attr_done = false;
    if (!attr_done) {
        cudaFuncSetAttribute(fused_gemm_kernel,
                             cudaFuncAttributeMaxDynamicSharedMemorySize, SMEM_DYN);
        attr_done = true;
    }

    round_w_kernel<<<(OUTC * KTOT + 1023) / 1024, 1024>>>(cw);
    offset_conv_kernel<<<BATCH * HH * 4, 128>>>(x, ow, ob);
    fused_gemm_kernel<<<NTOT / 64, 256, SMEM_DYN>>>(x, out);
}